// round 8
// baseline (speedup 1.0000x reference)
#include <cuda_runtime.h>
#include <cuda_bf16.h>
#include <cstddef>

#define COL   4096
#define TPB   256
#define NW    (TPB/32)     // 8 warps
#define VPT   16           // elements per thread (4 x float4)
#define RPB   8            // rows per block, software-pipelined

__global__ __launch_bounds__(TPB, 4) void layernorm_v2_kernel(
    const float* __restrict__ x,
    const float* __restrict__ alpha,
    const float* __restrict__ beta,
    float* __restrict__ out)
{
    __shared__ float  wsum[2][NW];
    __shared__ float  wvar[2][NW];
    __shared__ float4 rtab[TPB * 4];    // 16 KB: per-thread reciprocals 1/(i+1)

    const int tid  = threadIdx.x;
    const int lane = tid & 31;
    const int wid  = tid >> 5;
    const int f4   = 4 * tid;           // thread owns float4 indices f4..f4+3

    // ---- once per block: reciprocal table (amortized over RPB rows) ----
    float C = 0.0f;                     // sum of r^2 over this thread's 16
    {
        const int e0 = VPT * tid;
        #pragma unroll
        for (int j = 0; j < 4; ++j) {
            float4 r;
            r.x = 1.0f / (float)(e0 + 4 * j + 1);
            r.y = 1.0f / (float)(e0 + 4 * j + 2);
            r.z = 1.0f / (float)(e0 + 4 * j + 3);
            r.w = 1.0f / (float)(e0 + 4 * j + 4);
            rtab[f4 + j] = r;
            C += (r.x * r.x + r.y * r.y) + (r.z * r.z + r.w * r.w);
        }
    }

    const float al = __ldg(alpha);
    const float be = __ldg(beta);

    const size_t row0 = (size_t)blockIdx.x * RPB;

    // prologue: load first row (4 x LDG.128)
    float4 a0 = ((const float4*)(x + row0 * COL))[f4 + 0];
    float4 a1 = ((const float4*)(x + row0 * COL))[f4 + 1];
    float4 a2 = ((const float4*)(x + row0 * COL))[f4 + 2];
    float4 a3 = ((const float4*)(x + row0 * COL))[f4 + 3];

    __syncthreads();   // rtab visible (block start only)

    #pragma unroll 1
    for (int k = 0; k < RPB; ++k) {
        const int buf = k & 1;

        // prefetch next row before any barrier (LDG issue crosses BAR.SYNC)
        float4 b0, b1, b2, b3;
        if (k + 1 < RPB) {
            const float4* xn = (const float4*)(x + (row0 + k + 1) * COL);
            b0 = xn[f4 + 0];
            b1 = xn[f4 + 1];
            b2 = xn[f4 + 2];
            b3 = xn[f4 + 3];
        }

        // ---- local scan + A,B accumulation; p_i and q_i die immediately ----
        float run = 0.0f, A = 0.0f, B = 0.0f;
        {
            const float4 r = rtab[f4 + 0];
            float p, q;
            p = run + a0.x; q = a0.x - p * r.x; A += q * q; B += q * r.x;
            p += a0.y;      q = a0.y - p * r.y; A += q * q; B += q * r.y;
            p += a0.z;      q = a0.z - p * r.z; A += q * q; B += q * r.z;
            p += a0.w;      q = a0.w - p * r.w; A += q * q; B += q * r.w;
            run = p;
        }
        {
            const float4 r = rtab[f4 + 1];
            float p, q;
            p = run + a1.x; q = a1.x - p * r.x; A += q * q; B += q * r.x;
            p += a1.y;      q = a1.y - p * r.y; A += q * q; B += q * r.y;
            p += a1.z;      q = a1.z - p * r.z; A += q * q; B += q * r.z;
            p += a1.w;      q = a1.w - p * r.w; A += q * q; B += q * r.w;
            run = p;
        }
        {
            const float4 r = rtab[f4 + 2];
            float p, q;
            p = run + a2.x; q = a2.x - p * r.x; A += q * q; B += q * r.x;
            p += a2.y;      q = a2.y - p * r.y; A += q * q; B += q * r.y;
            p += a2.z;      q = a2.z - p * r.z; A += q * q; B += q * r.z;
            p += a2.w;      q = a2.w - p * r.w; A += q * q; B += q * r.w;
            run = p;
        }
        {
            const float4 r = rtab[f4 + 3];
            float p, q;
            p = run + a3.x; q = a3.x - p * r.x; A += q * q; B += q * r.x;
            p += a3.y;      q = a3.y - p * r.y; A += q * q; B += q * r.y;
            p += a3.z;      q = a3.z - p * r.z; A += q * q; B += q * r.z;
            p += a3.w;      q = a3.w - p * r.w; A += q * q; B += q * r.w;
            run = p;
        }
        const float tot = run;

        // warp inclusive scan of thread totals (5 shfls)
        float v = tot;
        #pragma unroll
        for (int o = 1; o < 32; o <<= 1) {
            float s = __shfl_up_sync(0xffffffffu, v, o);
            if (lane >= o) v += s;
        }
        const float l = v - tot;            // warp-local exclusive prefix

        if (lane == 31) wsum[buf][wid] = v;
        __syncthreads();                    // BAR 1

        // redundant cross-warp scan of 8 totals (3 shfls, every warp)
        float t8 = (lane < NW) ? wsum[buf][lane] : 0.0f;
        #pragma unroll
        for (int o = 1; o < NW; o <<= 1) {
            float s = __shfl_up_sync(0xffffffffu, t8, o);
            if (lane >= o) t8 += s;
        }
        const float total = __shfl_sync(0xffffffffu, t8, NW - 1);
        float woff = __shfl_sync(0xffffffffu, t8, (wid == 0) ? 0 : (wid - 1));
        if (wid == 0) woff = 0.0f;

        const float e = woff + l;           // block-exclusive prefix
        float acc = A - 2.0f * e * B + e * e * C;

        #pragma unroll
        for (int o = 16; o > 0; o >>= 1) acc += __shfl_xor_sync(0xffffffffu, acc, o);
        if (lane == 0) wvar[buf][wid] = acc;
        __syncthreads();                    // BAR 2

        const float u0 = wvar[buf][0] + wvar[buf][1];
        const float u1 = wvar[buf][2] + wvar[buf][3];
        const float u2 = wvar[buf][4] + wvar[buf][5];
        const float u3 = wvar[buf][6] + wvar[buf][7];
        const float var   = ((u0 + u1) + (u2 + u3)) * (1.0f / (float)(COL - 1));
        const float mean  = total * (1.0f / (float)COL);
        const float scale = al * rsqrtf(var + 1e-5f);
        const float shift = be - mean * scale;    // out = x*scale + shift

        float4* orow = (float4*)(out + (row0 + k) * COL);
        float4 o4;
        o4.x = a0.x * scale + shift; o4.y = a0.y * scale + shift;
        o4.z = a0.z * scale + shift; o4.w = a0.w * scale + shift;
        orow[f4 + 0] = o4;
        o4.x = a1.x * scale + shift; o4.y = a1.y * scale + shift;
        o4.z = a1.z * scale + shift; o4.w = a1.w * scale + shift;
        orow[f4 + 1] = o4;
        o4.x = a2.x * scale + shift; o4.y = a2.y * scale + shift;
        o4.z = a2.z * scale + shift; o4.w = a2.w * scale + shift;
        orow[f4 + 2] = o4;
        o4.x = a3.x * scale + shift; o4.y = a3.y * scale + shift;
        o4.z = a3.z * scale + shift; o4.w = a3.w * scale + shift;
        orow[f4 + 3] = o4;

        a0 = b0; a1 = b1; a2 = b2; a3 = b3;
    }
}

extern "C" void kernel_launch(void* const* d_in, const int* in_sizes, int n_in,
                              void* d_out, int out_size)
{
    const float* x     = (const float*)d_in[0];
    const float* alpha = (const float*)d_in[1];
    const float* beta  = (const float*)d_in[2];
    float*       out   = (float*)d_out;

    const int rows = in_sizes[0] / COL;
    const int grid = rows / RPB;               // 4096 blocks x 8 rows

    layernorm_v2_kernel<<<grid, TPB>>>(x, alpha, beta, out);
}

// round 9
// speedup vs baseline: 1.1874x; 1.1874x over previous
#include <cuda_runtime.h>
#include <cuda_bf16.h>
#include <cstddef>

#define COL   4096
#define TPB   256
#define NW    (TPB/32)     // 8 warps
#define VPT   16           // elements per thread (4 x float4)
#define RPB   8            // rows per block, software-pipelined

__global__ __launch_bounds__(TPB, 4) void layernorm_v2_kernel(
    const float* __restrict__ x,
    const float* __restrict__ alpha,
    const float* __restrict__ beta,
    float* __restrict__ out)
{
    __shared__ float  wsum[2][NW];
    __shared__ float  wvar[2][NW];
    // j-major layout: rtab[j*TPB + tid] -> LDS.128 lane-contiguous, conflict-free
    __shared__ float4 rtab[4 * TPB];    // 16 KB reciprocals 1/(i+1)

    const int tid  = threadIdx.x;
    const int lane = tid & 31;
    const int wid  = tid >> 5;
    const int f4   = 4 * tid;           // thread owns float4 indices f4..f4+3

    // ---- once per block: reciprocal table (amortized over RPB rows) ----
    float C = 0.0f;                     // sum of r^2 over this thread's 16
    {
        const int e0 = VPT * tid;
        #pragma unroll
        for (int j = 0; j < 4; ++j) {
            float4 r;
            r.x = 1.0f / (float)(e0 + 4 * j + 1);
            r.y = 1.0f / (float)(e0 + 4 * j + 2);
            r.z = 1.0f / (float)(e0 + 4 * j + 3);
            r.w = 1.0f / (float)(e0 + 4 * j + 4);
            rtab[j * TPB + tid] = r;    // conflict-free layout
            C += (r.x * r.x + r.y * r.y) + (r.z * r.z + r.w * r.w);
        }
    }

    const float al = __ldg(alpha);
    const float be = __ldg(beta);

    const size_t row0 = (size_t)blockIdx.x * RPB;

    // prologue: load first row (4 x LDG.128)
    float4 a0 = ((const float4*)(x + row0 * COL))[f4 + 0];
    float4 a1 = ((const float4*)(x + row0 * COL))[f4 + 1];
    float4 a2 = ((const float4*)(x + row0 * COL))[f4 + 2];
    float4 a3 = ((const float4*)(x + row0 * COL))[f4 + 3];

    __syncthreads();   // rtab visible (block start only)

    #pragma unroll 1
    for (int k = 0; k < RPB; ++k) {
        const int buf = k & 1;

        // prefetch next row before any barrier (LDG issue crosses BAR.SYNC)
        float4 b0, b1, b2, b3;
        if (k + 1 < RPB) {
            const float4* xn = (const float4*)(x + (row0 + k + 1) * COL);
            b0 = xn[f4 + 0];
            b1 = xn[f4 + 1];
            b2 = xn[f4 + 2];
            b3 = xn[f4 + 3];
        }

        // ---- local scan + A,B accumulation (p,q die immediately) ----
        float run = 0.0f, A = 0.0f, B = 0.0f;
        {
            const float4 r = rtab[0 * TPB + tid];
            float p, q;
            p = run + a0.x; q = a0.x - p * r.x; A += q * q; B += q * r.x;
            p += a0.y;      q = a0.y - p * r.y; A += q * q; B += q * r.y;
            p += a0.z;      q = a0.z - p * r.z; A += q * q; B += q * r.z;
            p += a0.w;      q = a0.w - p * r.w; A += q * q; B += q * r.w;
            run = p;
        }
        {
            const float4 r = rtab[1 * TPB + tid];
            float p, q;
            p = run + a1.x; q = a1.x - p * r.x; A += q * q; B += q * r.x;
            p += a1.y;      q = a1.y - p * r.y; A += q * q; B += q * r.y;
            p += a1.z;      q = a1.z - p * r.z; A += q * q; B += q * r.z;
            p += a1.w;      q = a1.w - p * r.w; A += q * q; B += q * r.w;
            run = p;
        }
        {
            const float4 r = rtab[2 * TPB + tid];
            float p, q;
            p = run + a2.x; q = a2.x - p * r.x; A += q * q; B += q * r.x;
            p += a2.y;      q = a2.y - p * r.y; A += q * q; B += q * r.y;
            p += a2.z;      q = a2.z - p * r.z; A += q * q; B += q * r.z;
            p += a2.w;      q = a2.w - p * r.w; A += q * q; B += q * r.w;
            run = p;
        }
        {
            const float4 r = rtab[3 * TPB + tid];
            float p, q;
            p = run + a3.x; q = a3.x - p * r.x; A += q * q; B += q * r.x;
            p += a3.y;      q = a3.y - p * r.y; A += q * q; B += q * r.y;
            p += a3.z;      q = a3.z - p * r.z; A += q * q; B += q * r.z;
            p += a3.w;      q = a3.w - p * r.w; A += q * q; B += q * r.w;
            run = p;
        }
        const float tot = run;

        // warp inclusive scan of thread totals (5 shfls)
        float v = tot;
        #pragma unroll
        for (int o = 1; o < 32; o <<= 1) {
            float s = __shfl_up_sync(0xffffffffu, v, o);
            if (lane >= o) v += s;
        }
        const float l = v - tot;            // warp-local exclusive prefix

        if (lane == 31) wsum[buf][wid] = v;
        __syncthreads();                    // BAR 1

        // redundant cross-warp scan of 8 totals (3 shfls, every warp)
        float t8 = (lane < NW) ? wsum[buf][lane] : 0.0f;
        #pragma unroll
        for (int o = 1; o < NW; o <<= 1) {
            float s = __shfl_up_sync(0xffffffffu, t8, o);
            if (lane >= o) t8 += s;
        }
        const float total = __shfl_sync(0xffffffffu, t8, NW - 1);
        float woff = __shfl_sync(0xffffffffu, t8, (wid == 0) ? 0 : (wid - 1));
        if (wid == 0) woff = 0.0f;

        const float e = woff + l;           // block-exclusive prefix
        float acc = A - 2.0f * e * B + e * e * C;

        #pragma unroll
        for (int o = 16; o > 0; o >>= 1) acc += __shfl_xor_sync(0xffffffffu, acc, o);
        if (lane == 0) wvar[buf][wid] = acc;
        __syncthreads();                    // BAR 2

        const float u0 = wvar[buf][0] + wvar[buf][1];
        const float u1 = wvar[buf][2] + wvar[buf][3];
        const float u2 = wvar[buf][4] + wvar[buf][5];
        const float u3 = wvar[buf][6] + wvar[buf][7];
        const float var   = ((u0 + u1) + (u2 + u3)) * (1.0f / (float)(COL - 1));
        const float mean  = total * (1.0f / (float)COL);
        const float scale = al * rsqrtf(var + 1e-5f);
        const float shift = be - mean * scale;    // out = x*scale + shift

        float4* orow = (float4*)(out + (row0 + k) * COL);
        float4 o4;
        o4.x = a0.x * scale + shift; o4.y = a0.y * scale + shift;
        o4.z = a0.z * scale + shift; o4.w = a0.w * scale + shift;
        orow[f4 + 0] = o4;
        o4.x = a1.x * scale + shift; o4.y = a1.y * scale + shift;
        o4.z = a1.z * scale + shift; o4.w = a1.w * scale + shift;
        orow[f4 + 1] = o4;
        o4.x = a2.x * scale + shift; o4.y = a2.y * scale + shift;
        o4.z = a2.z * scale + shift; o4.w = a2.w * scale + shift;
        orow[f4 + 2] = o4;
        o4.x = a3.x * scale + shift; o4.y = a3.y * scale + shift;
        o4.z = a3.z * scale + shift; o4.w = a3.w * scale + shift;
        orow[f4 + 3] = o4;

        a0 = b0; a1 = b1; a2 = b2; a3 = b3;
    }
}

extern "C" void kernel_launch(void* const* d_in, const int* in_sizes, int n_in,
                              void* d_out, int out_size)
{
    const float* x     = (const float*)d_in[0];
    const float* alpha = (const float*)d_in[1];
    const float* beta  = (const float*)d_in[2];
    float*       out   = (float*)d_out;

    const int rows = in_sizes[0] / COL;
    const int grid = rows / RPB;               // 4096 blocks x 8 rows

    layernorm_v2_kernel<<<grid, TPB>>>(x, alpha, beta, out);
}

// round 11
// speedup vs baseline: 1.2327x; 1.0382x over previous
#include <cuda_runtime.h>
#include <cuda_bf16.h>
#include <cstddef>

#define COL    4096
#define TPB    256
#define WPB    (TPB/32)     // 8 warps per block, one row per warp
#define NCHUNK 16           // 16 chunks x 256 elements
#define F4C    64           // float4 per chunk

// Reciprocal table 1/(i+1), filled each launch (graph-capturable, no allocs).
__device__ float g_rinv[COL];

__global__ void rinv_init_kernel() {
    int i = blockIdx.x * blockDim.x + threadIdx.x;
    if (i < COL) g_rinv[i] = 1.0f / (float)(i + 1);
}

// ---- 32-byte L2-steered accesses (.v4.b64 required for evict hints) ----
__device__ __forceinline__ void ldg_el_32(const float4* p, float4& a, float4& b) {
    unsigned long long q0, q1, q2, q3;
    asm volatile("ld.global.nc.L2::evict_last.v4.b64 {%0,%1,%2,%3}, [%4];"
                 : "=l"(q0), "=l"(q1), "=l"(q2), "=l"(q3) : "l"(p));
    a.x = __uint_as_float((unsigned)q0); a.y = __uint_as_float((unsigned)(q0 >> 32));
    a.z = __uint_as_float((unsigned)q1); a.w = __uint_as_float((unsigned)(q1 >> 32));
    b.x = __uint_as_float((unsigned)q2); b.y = __uint_as_float((unsigned)(q2 >> 32));
    b.z = __uint_as_float((unsigned)q3); b.w = __uint_as_float((unsigned)(q3 >> 32));
}
__device__ __forceinline__ void ldg_ef_32(const float4* p, float4& a, float4& b) {
    unsigned long long q0, q1, q2, q3;
    asm volatile("ld.global.nc.L2::evict_first.v4.b64 {%0,%1,%2,%3}, [%4];"
                 : "=l"(q0), "=l"(q1), "=l"(q2), "=l"(q3) : "l"(p));
    a.x = __uint_as_float((unsigned)q0); a.y = __uint_as_float((unsigned)(q0 >> 32));
    a.z = __uint_as_float((unsigned)q1); a.w = __uint_as_float((unsigned)(q1 >> 32));
    b.x = __uint_as_float((unsigned)q2); b.y = __uint_as_float((unsigned)(q2 >> 32));
    b.z = __uint_as_float((unsigned)q3); b.w = __uint_as_float((unsigned)(q3 >> 32));
}
__device__ __forceinline__ void stg_ef_32(float4* p, float4 a, float4 b) {
    unsigned long long q0 = ((unsigned long long)__float_as_uint(a.y) << 32) | __float_as_uint(a.x);
    unsigned long long q1 = ((unsigned long long)__float_as_uint(a.w) << 32) | __float_as_uint(a.z);
    unsigned long long q2 = ((unsigned long long)__float_as_uint(b.y) << 32) | __float_as_uint(b.x);
    unsigned long long q3 = ((unsigned long long)__float_as_uint(b.w) << 32) | __float_as_uint(b.z);
    asm volatile("st.global.L2::evict_first.v4.b64 [%0], {%1,%2,%3,%4};"
                 :: "l"(p), "l"(q0), "l"(q1), "l"(q2), "l"(q3) : "memory");
}

__global__ __launch_bounds__(TPB) void layernorm_v2_kernel(
    const float* __restrict__ x,
    const float* __restrict__ alpha,
    const float* __restrict__ beta,
    float* __restrict__ out)
{
    const int lane = threadIdx.x & 31;
    const int wid  = threadIdx.x >> 5;
    const size_t row = (size_t)blockIdx.x * WPB + wid;

    const float4* xr  = (const float4*)(x + row * COL);
    const float4* rr  = (const float4*)g_rinv;
    float4*       orw = (float4*)(out + row * COL);

    const int l2 = lane * 2;   // lane owns f4 indices c*64 + 2*lane, +1 (32B pair)

    // ---- pass 1: sequential chunked scan + variance, double-buffered loads ----
    float4 c0, c1;
    ldg_el_32(xr + l2, c0, c1);
    float carry = 0.0f;        // row prefix entering current chunk
    float acc   = 0.0f;        // variance accumulator

    #pragma unroll 1
    for (int c = 0; c < NCHUNK; ++c) {
        float4 n0, n1;
        if (c + 1 < NCHUNK) {                    // prefetch next chunk, pinned in L2
            ldg_el_32(xr + (c + 1) * F4C + l2, n0, n1);
        }
        const float4 r0 = rr[c * F4C + l2];      // L1-resident table
        const float4 r1 = rr[c * F4C + l2 + 1];

        // local inclusive scan of the 8-chunk
        const float p0 = c0.x;
        const float p1 = p0 + c0.y;
        const float p2 = p1 + c0.z;
        const float p3 = p2 + c0.w;
        const float p4 = p3 + c1.x;
        const float p5 = p4 + c1.y;
        const float p6 = p5 + c1.z;
        const float p7 = p6 + c1.w;
        const float tot = p7;

        // warp scan of lane totals
        float v = tot;
        #pragma unroll
        for (int o = 1; o < 32; o <<= 1) {
            float t = __shfl_up_sync(0xffffffffu, v, o);
            if (lane >= o) v += t;
        }
        const float chunk_total = __shfl_sync(0xffffffffu, v, 31);
        const float excl = carry + (v - tot);    // row-prefix before this lane's 8

        float d0 = c0.x - (excl + p0) * r0.x;
        float d1 = c0.y - (excl + p1) * r0.y;
        float d2 = c0.z - (excl + p2) * r0.z;
        float d3 = c0.w - (excl + p3) * r0.w;
        float d4 = c1.x - (excl + p4) * r1.x;
        float d5 = c1.y - (excl + p5) * r1.y;
        float d6 = c1.z - (excl + p6) * r1.z;
        float d7 = c1.w - (excl + p7) * r1.w;
        acc += ((d0 * d0 + d1 * d1) + (d2 * d2 + d3 * d3))
             + ((d4 * d4 + d5 * d5) + (d6 * d6 + d7 * d7));

        carry += chunk_total;
        c0 = n0;
        c1 = n1;
    }

    // ---- finish stats (warp-local, no barriers) ----
    #pragma unroll
    for (int o = 16; o > 0; o >>= 1) acc += __shfl_xor_sync(0xffffffffu, acc, o);

    const float var   = acc   * (1.0f / (float)(COL - 1));
    const float mean  = carry * (1.0f / (float)COL);
    const float scale = __ldg(alpha) * rsqrtf(var + 1e-5f);
    const float shift = __ldg(beta) - mean * scale;   // out = x*scale + shift

    // ---- pass 2: re-read row (L2-pinned), release lines, stream out stores ----
    #pragma unroll 4
    for (int c = 0; c < NCHUNK; ++c) {
        float4 a, b;
        ldg_ef_32(xr + c * F4C + l2, a, b);
        float4 oa, ob;
        oa.x = a.x * scale + shift;
        oa.y = a.y * scale + shift;
        oa.z = a.z * scale + shift;
        oa.w = a.w * scale + shift;
        ob.x = b.x * scale + shift;
        ob.y = b.y * scale + shift;
        ob.z = b.z * scale + shift;
        ob.w = b.w * scale + shift;
        stg_ef_32(orw + c * F4C + l2, oa, ob);
    }
}

extern "C" void kernel_launch(void* const* d_in, const int* in_sizes, int n_in,
                              void* d_out, int out_size)
{
    const float* x     = (const float*)d_in[0];
    const float* alpha = (const float*)d_in[1];
    const float* beta  = (const float*)d_in[2];
    float*       out   = (float*)d_out;

    const int rows = in_sizes[0] / COL;
    const int grid = rows / WPB;                 // 4096 blocks x 8 warp-rows

    rinv_init_kernel<<<(COL + 255) / 256, 256>>>();
    layernorm_v2_kernel<<<grid, TPB>>>(x, alpha, beta, out);
}